// round 7
// baseline (speedup 1.0000x reference)
#include <cuda_runtime.h>
#include <cuda_fp16.h>
#include <math.h>

#define S_LEN 8192
#define TAGS 2048
#define RPB 14
#define NB 147                 // 146*14 + 4 = 2048 rows
#define TPB 512
#define NWARP 16
#define JW (TAGS / NWARP)      // 128 j-columns per warp
#define JL (JW / 2)            // 64 j per lane
#define EH2 (JL / 2)           // 32 half2 E registers per lane
#define PSTRIDE 20
#define ALPHA 8.0f
#define START_IDX 0
#define END_IDX 1
#define POLL0 352              // poller threads are tid in [352, 352+NB)

// 64B publication record: 14 values + block max + epoch, tag released last.
struct __align__(64) Pub {
    float w[14];
    unsigned maxbits;          // +56: {maxbits, epoch} written as one release b64
    unsigned epoch;            // +60
};

__device__ Pub g_pub[2][NB];
__device__ float g_Mbuf[S_LEN];   // written by block 0 only; read in its epilogue

__global__ void crf_init() {
    int i = blockIdx.x * blockDim.x + threadIdx.x;
    if (i < 2 * NB) {
        int par = i / NB, b = i % NB;
        Pub p;
#pragma unroll
        for (int k = 0; k < 14; k++) p.w[k] = 0.f;
        p.maxbits = 0u; p.epoch = 0u;
        if (par == 0 && b == 0) {          // r_0 = onehot(START_IDX), max = 1.0
            p.w[START_IDX] = 1.0f;
            p.maxbits = __float_as_uint(1.0f);
        }
        g_pub[par][b] = p;
    }
}

__device__ __forceinline__ __half2 f_as_h2(const float& f) {
    return *reinterpret_cast<const __half2*>(&f);
}
__device__ __forceinline__ float4 add4(float4 a, float4 b) {
    return make_float4(a.x + b.x, a.y + b.y, a.z + b.z, a.w + b.w);
}
__device__ __forceinline__ unsigned umax2(unsigned a, unsigned b) { return a > b ? a : b; }

// Poll one producer tag until epoch >= t; fetch its 14 values into smem vsrc.
__device__ __forceinline__ unsigned poll_fetch(int p, int t, int parity, float* vsrc) {
    const char* src = (const char*)&g_pub[parity][p];
    unsigned long long fe;
    do {
        asm volatile("ld.acquire.gpu.global.b64 %0, [%1];"
                     : "=l"(fe) : "l"(src + 56) : "memory");
    } while ((unsigned)(fe >> 32) < (unsigned)t);
    uint4 a = __ldcg((const uint4*)(src));
    uint4 c = __ldcg((const uint4*)(src + 16));
    uint4 e = __ldcg((const uint4*)(src + 32));
    uint2 d = __ldcg((const uint2*)(src + 48));
    uint2* dst = reinterpret_cast<uint2*>(vsrc) + p * 7;   // 14 floats = 7 uint2
    dst[0] = make_uint2(a.x, a.y); dst[1] = make_uint2(a.z, a.w);
    dst[2] = make_uint2(c.x, c.y); dst[3] = make_uint2(c.z, c.w);
    dst[4] = make_uint2(e.x, e.y); dst[5] = make_uint2(e.z, e.w);
    dst[6] = d;
    return (unsigned)fe;                                    // producer's block max
}

__global__ void __launch_bounds__(TPB, 1) crf_main(const float* __restrict__ h,
                                                   const float* __restrict__ tr,
                                                   float* __restrict__ out) {
    __shared__ float vsrc[NB * RPB + 6];        // 2058 (+pad): current vector, fp32
    __shared__ __half2 vbuf[TAGS / 2];          // 4KB: scaled fp16 vector
    __shared__ float P[2 * RPB][PSTRIDE];       // transposed partials
    __shared__ float pw[16];                    // warp0 gather for publication
    __shared__ unsigned wmax[5];                // per-poller-warp maxes
    __shared__ double redd[TPB];                // epilogue scratch

    const int tid = threadIdx.x;
    const int warp = tid >> 5, lane = tid & 31;
    const int b = blockIdx.x;
    const int row0 = b * RPB;
    int nrows = TAGS - row0; if (nrows > RPB) nrows = RPB;

    const bool act = lane < 2 * RPB;
    const int row = (lane < RPB) ? lane : lane - RPB;
    const int jh = (lane >= RPB) ? 1 : 0;

    const int p = tid - POLL0;
    const bool poller = (p >= 0) && (p < NB);
    const bool pollw = (tid >= POLL0);          // warps 11..15

    // ---- One-time: this lane's E chunk = exp(transitions) -> 32 half2 registers ----
    __half2 E2[EH2];
    if (act && row < nrows) {
        const float* trow = tr + (size_t)(row0 + row) * TAGS + warp * JW + jh * JL;
#pragma unroll
        for (int q = 0; q < EH2; q++)
            E2[q] = __floats2half2_rn(__expf(trow[2 * q]), __expf(trow[2 * q + 1]));
    } else {
#pragma unroll
        for (int q = 0; q < EH2; q++) E2[q] = __floats2half2_rn(0.f, 0.f);
    }

    const float4* v4base = reinterpret_cast<const float4*>(vbuf) + (warp * 16 + jh * 8);
    const bool comb = (warp == 0) && (lane < nrows);

    float hv = comb ? __ldcg(h + row0 + lane) : 0.f;   // one step ahead

    for (int t = 0; t < S_LEN; t++) {
        // ---- phase 1: acquire r_t (tagged structs), REDUX block maxes ----
        unsigned mx = 0;
        if (poller) mx = poll_fetch(p, t, t & 1, vsrc);
        if (pollw) {
            unsigned wm = __reduce_max_sync(0xffffffffu, mx);
            if (lane == 0) wmax[warp - 11] = wm;
        }
        float ehv = __expf(hv);                        // off critical path for pollers
        if (comb && t + 1 < S_LEN)
            hv = __ldcg(h + (size_t)(t + 1) * TAGS + row0 + lane);
        __syncthreads();

        // ---- phase 2: global max -> scale, convert 4 own j-values into vbuf ----
        unsigned mm = umax2(umax2(umax2(wmax[0], wmax[1]), umax2(wmax[2], wmax[3])), wmax[4]);
        float m = __uint_as_float(mm);
        if (b == 0 && tid == 0) __stcg(&g_Mbuf[t], m);
        float s = __fdividef(ALPHA, m);
        float4 x = *reinterpret_cast<const float4*>(vsrc + 4 * tid);
        vbuf[2 * tid]     = __floats2half2_rn(x.x * s, x.y * s);
        vbuf[2 * tid + 1] = __floats2half2_rn(x.z * s, x.w * s);
        __syncwarp();   // vbuf slice produced & consumed within this warp

        // ---- dot fragments: 4 chains of 8 half2 (16 fp16 terms each) ----
        float f0 = 0.f, f1 = 0.f;
#pragma unroll
        for (int c = 0; c < 4; c++) {
            float4 va = v4base[2 * c];
            float4 vb = v4base[2 * c + 1];
            __half2 acc = __hmul2(E2[8 * c + 0], f_as_h2(va.x));
            acc = __hfma2(E2[8 * c + 1], f_as_h2(va.y), acc);
            acc = __hfma2(E2[8 * c + 2], f_as_h2(va.z), acc);
            acc = __hfma2(E2[8 * c + 3], f_as_h2(va.w), acc);
            acc = __hfma2(E2[8 * c + 4], f_as_h2(vb.x), acc);
            acc = __hfma2(E2[8 * c + 5], f_as_h2(vb.y), acc);
            acc = __hfma2(E2[8 * c + 6], f_as_h2(vb.z), acc);
            acc = __hfma2(E2[8 * c + 7], f_as_h2(vb.w), acc);
            float2 ff = __half22float2(acc);
            f0 += ff.x; f1 += ff.y;
        }
        if (act) P[lane][warp] = f0 + f1;
        __syncthreads();

        // ---- combine (warp 0) and publish tagged record ----
        if (warp == 0) {
            float wv = 0.f;
            if (comb) {
                const float4* Pr = reinterpret_cast<const float4*>(P[lane]);
                const float4* Qr = reinterpret_cast<const float4*>(P[lane + RPB]);
                float4 s4 = add4(add4(add4(Pr[0], Pr[1]), add4(Pr[2], Pr[3])),
                                 add4(add4(Qr[0], Qr[1]), add4(Qr[2], Qr[3])));
                float sum = (s4.x + s4.y) + (s4.z + s4.w);
                wv = ehv * sum;
            }
            if (lane < RPB) pw[lane] = wv;
            unsigned u = __reduce_max_sync(0xffffffffu, __float_as_uint(wv));
            __syncwarp();
            if (lane == 0) {
                char* dst = (char*)&g_pub[(t + 1) & 1][b];
                __stcg((float4*)(dst),      *reinterpret_cast<float4*>(pw));
                __stcg((float4*)(dst + 16), *reinterpret_cast<float4*>(pw + 4));
                __stcg((float4*)(dst + 32), *reinterpret_cast<float4*>(pw + 8));
                __stcg((float2*)(dst + 48), *reinterpret_cast<float2*>(pw + 12));
                unsigned long long tag = ((unsigned long long)(unsigned)(t + 1) << 32) | u;
                asm volatile("st.release.gpu.global.b64 [%0], %1;"
                             :: "l"(dst + 56), "l"(tag) : "memory");
            }
        }
        // (next iteration's phase-1 syncthreads gates smem reuse)
    }

    // ---- epilogue: block 0 gathers r_S, computes log Z ----
    if (b == 0) {
        if (poller) (void)poll_fetch(p, S_LEN, S_LEN & 1, vsrc);
        __syncthreads();

        float* redf = reinterpret_cast<float*>(vbuf);
        float dpart = 0.f;
        for (int j = tid; j < TAGS; j += TPB)
            dpart += vsrc[j] * __expf(tr[(size_t)END_IDX * TAGS + j]);
        double lpart = 0.0;
        for (int t = tid; t < S_LEN; t += TPB)
            lpart += log((double)__ldcg(&g_Mbuf[t]));
        redf[tid] = dpart;
        redd[tid] = lpart;
        __syncthreads();
        for (int off = TPB / 2; off > 0; off >>= 1) {
            if (tid < off) { redf[tid] += redf[tid + off]; redd[tid] += redd[tid + off]; }
            __syncthreads();
        }
        if (tid == 0)
            out[0] = (float)(redd[0] + log((double)redf[0]) -
                             (double)S_LEN * log((double)ALPHA));
    }
}

extern "C" void kernel_launch(void* const* d_in, const int* in_sizes, int n_in,
                              void* d_out, int out_size) {
    const float* a = (const float*)d_in[0];
    const float* bb = (const float*)d_in[1];
    const float* h;
    const float* tr;
    if (in_sizes[0] == S_LEN * TAGS) { h = a; tr = bb; }
    else { h = bb; tr = a; }

    crf_init<<<2, 256>>>();
    crf_main<<<NB, TPB>>>(h, tr, (float*)d_out);
}

// round 8
// speedup vs baseline: 1.7738x; 1.7738x over previous
#include <cuda_runtime.h>
#include <cuda_fp16.h>
#include <math.h>

#define S_LEN 8192
#define TAGS 2048
#define RPB 14
#define NB 147                 // 146*14 + 4 = 2048 rows
#define TPB 512
#define NWARP 16
#define JW (TAGS / NWARP)      // 128 j-columns per warp
#define JL (JW / 2)            // 64 j per lane
#define EH2 (JL / 2)           // 32 half2 E registers per lane
#define PSTRIDE 20
#define ALPHA 8.0f
#define START_IDX 0
#define END_IDX 1

typedef unsigned long long ull;

// Tagged carried vector: each word = {low: f32 bits of value, high: epoch}.
// Published with one atomic 8B relaxed store; the tag IS the readiness flag.
__device__ ull g_tag[2][TAGS];
__device__ float g_Mbuf[S_LEN];   // per-step global max (block 0 writes; epilogue reads)

__global__ void crf_init() {
    int i = blockIdx.x * blockDim.x + threadIdx.x;
    if (i < TAGS) {
        // buffer 0 holds r_0 (epoch 0): onehot(START_IDX)
        g_tag[0][i] = (i == START_IDX) ? (ull)0x3f800000u : 0ull;
        // buffer 1: epoch sentinel that never matches any t in [0, S_LEN]
        g_tag[1][i] = 0xFFFFFFFF00000000ull;
    }
}

__device__ __forceinline__ __half2 f_as_h2(const float& f) {
    return *reinterpret_cast<const __half2*>(&f);
}
__device__ __forceinline__ float4 add4(float4 a, float4 b) {
    return make_float4(a.x + b.x, a.y + b.y, a.z + b.z, a.w + b.w);
}
__device__ __forceinline__ unsigned umax2(unsigned a, unsigned b) { return a > b ? a : b; }

__global__ void __launch_bounds__(TPB, 1) crf_main(const float* __restrict__ h,
                                                   const float* __restrict__ tr,
                                                   float* __restrict__ out) {
    __shared__ __half2 vbuf[TAGS / 2];          // 4KB: scaled fp16 vector (warp-private slices)
    __shared__ float P[2 * RPB][PSTRIDE];       // transposed partials
    __shared__ unsigned wmax[NWARP];            // per-warp value-max
    __shared__ double redd[TPB];                // epilogue scratch

    const int tid = threadIdx.x;
    const int warp = tid >> 5, lane = tid & 31;
    const int b = blockIdx.x;
    const int row0 = b * RPB;
    int nrows = TAGS - row0; if (nrows > RPB) nrows = RPB;

    const bool act = lane < 2 * RPB;
    const int row = (lane < RPB) ? lane : lane - RPB;
    const int jh = (lane >= RPB) ? 1 : 0;

    // ---- One-time: this lane's E chunk = exp(transitions) -> 32 half2 registers ----
    __half2 E2[EH2];
    if (act && row < nrows) {
        const float* trow = tr + (size_t)(row0 + row) * TAGS + warp * JW + jh * JL;
#pragma unroll
        for (int q = 0; q < EH2; q++)
            E2[q] = __floats2half2_rn(__expf(trow[2 * q]), __expf(trow[2 * q + 1]));
    } else {
#pragma unroll
        for (int q = 0; q < EH2; q++) E2[q] = __floats2half2_rn(0.f, 0.f);
    }

    const float4* v4base = reinterpret_cast<const float4*>(vbuf) + (warp * 16 + jh * 8);
    const bool comb = (warp == 0) && (lane < nrows);

    float hv = comb ? __ldcg(h + row0 + lane) : 0.f;   // one step ahead

    for (int t = 0; t < S_LEN; t++) {
        // ---- off critical path: exp of current emissions, prefetch next step's ----
        float ehv = __expf(hv);
        if (comb && t + 1 < S_LEN)
            hv = __ldcg(h + (size_t)(t + 1) * TAGS + row0 + lane);

        // ---- poll own 4 tagged values of r_t (the probe IS the data load) ----
        const ull* src = &g_tag[t & 1][4 * tid];
        const unsigned tu = (unsigned)t;
        ull q0, q1, q2, q3;
        do {
            asm volatile("ld.relaxed.gpu.global.b64 %0, [%1];" : "=l"(q0) : "l"(src));
            asm volatile("ld.relaxed.gpu.global.b64 %0, [%1];" : "=l"(q1) : "l"(src + 1));
            asm volatile("ld.relaxed.gpu.global.b64 %0, [%1];" : "=l"(q2) : "l"(src + 2));
            asm volatile("ld.relaxed.gpu.global.b64 %0, [%1];" : "=l"(q3) : "l"(src + 3));
        } while ((unsigned)(q0 >> 32) != tu || (unsigned)(q1 >> 32) != tu ||
                 (unsigned)(q2 >> 32) != tu || (unsigned)(q3 >> 32) != tu);

        // ---- block-wide max of r_t (values >= 0: uint order == float order) ----
        unsigned u = umax2(umax2((unsigned)q0, (unsigned)q1),
                           umax2((unsigned)q2, (unsigned)q3));
        u = __reduce_max_sync(0xffffffffu, u);
        if (lane == 0) wmax[warp] = u;
        __syncthreads();
        uint4 A = *reinterpret_cast<const uint4*>(wmax);
        uint4 B = *reinterpret_cast<const uint4*>(wmax + 4);
        uint4 C = *reinterpret_cast<const uint4*>(wmax + 8);
        uint4 D = *reinterpret_cast<const uint4*>(wmax + 12);
        unsigned mm = umax2(umax2(umax2(A.x, A.y), umax2(A.z, A.w)),
                            umax2(umax2(umax2(B.x, B.y), umax2(B.z, B.w)),
                                  umax2(umax2(umax2(C.x, C.y), umax2(C.z, C.w)),
                                        umax2(umax2(D.x, D.y), umax2(D.z, D.w)))));
        float m = __uint_as_float(mm);
        if (b == 0 && tid == 0) __stcg(&g_Mbuf[t], m);

        // ---- scale + fp16 convert own 4 values into warp-private vbuf slice ----
        float s = __fdividef(ALPHA, m);
        vbuf[2 * tid] = __floats2half2_rn(__uint_as_float((unsigned)q0) * s,
                                          __uint_as_float((unsigned)q1) * s);
        vbuf[2 * tid + 1] = __floats2half2_rn(__uint_as_float((unsigned)q2) * s,
                                              __uint_as_float((unsigned)q3) * s);
        __syncwarp();

        // ---- 64-j dot fragment per lane: 4 chains of 8 half2 ----
        float f0 = 0.f, f1 = 0.f;
#pragma unroll
        for (int c = 0; c < 4; c++) {
            float4 va = v4base[2 * c];
            float4 vb = v4base[2 * c + 1];
            __half2 acc = __hmul2(E2[8 * c + 0], f_as_h2(va.x));
            acc = __hfma2(E2[8 * c + 1], f_as_h2(va.y), acc);
            acc = __hfma2(E2[8 * c + 2], f_as_h2(va.z), acc);
            acc = __hfma2(E2[8 * c + 3], f_as_h2(va.w), acc);
            acc = __hfma2(E2[8 * c + 4], f_as_h2(vb.x), acc);
            acc = __hfma2(E2[8 * c + 5], f_as_h2(vb.y), acc);
            acc = __hfma2(E2[8 * c + 6], f_as_h2(vb.z), acc);
            acc = __hfma2(E2[8 * c + 7], f_as_h2(vb.w), acc);
            float2 ff = __half22float2(acc);
            f0 += ff.x; f1 += ff.y;
        }
        if (act) P[lane][warp] = f0 + f1;
        __syncthreads();

        // ---- combine (warp 0) and publish tagged values of r_{t+1} ----
        if (comb) {
            const float4* Pr = reinterpret_cast<const float4*>(P[lane]);
            const float4* Qr = reinterpret_cast<const float4*>(P[lane + RPB]);
            float4 s4 = add4(add4(add4(Pr[0], Pr[1]), add4(Pr[2], Pr[3])),
                             add4(add4(Qr[0], Qr[1]), add4(Qr[2], Qr[3])));
            float sum = (s4.x + s4.y) + (s4.z + s4.w);
            float wv = ehv * sum;
            ull pub = ((ull)(unsigned)(t + 1) << 32) | (ull)__float_as_uint(wv);
            asm volatile("st.relaxed.gpu.global.b64 [%0], %1;"
                         :: "l"(&g_tag[(t + 1) & 1][row0 + lane]), "l"(pub) : "memory");
        }
        // (next iteration's polls + syncthreads gate smem reuse)
    }

    // ---- epilogue: block 0 gathers r_S and computes log Z ----
    if (b == 0) {
        const ull* src = &g_tag[S_LEN & 1][4 * tid];
        const unsigned tu = (unsigned)S_LEN;
        ull q0, q1, q2, q3;
        do {
            asm volatile("ld.relaxed.gpu.global.b64 %0, [%1];" : "=l"(q0) : "l"(src));
            asm volatile("ld.relaxed.gpu.global.b64 %0, [%1];" : "=l"(q1) : "l"(src + 1));
            asm volatile("ld.relaxed.gpu.global.b64 %0, [%1];" : "=l"(q2) : "l"(src + 2));
            asm volatile("ld.relaxed.gpu.global.b64 %0, [%1];" : "=l"(q3) : "l"(src + 3));
        } while ((unsigned)(q0 >> 32) != tu || (unsigned)(q1 >> 32) != tu ||
                 (unsigned)(q2 >> 32) != tu || (unsigned)(q3 >> 32) != tu);

        const float* te = tr + (size_t)END_IDX * TAGS + 4 * tid;
        float dpart = __uint_as_float((unsigned)q0) * __expf(te[0])
                    + __uint_as_float((unsigned)q1) * __expf(te[1])
                    + __uint_as_float((unsigned)q2) * __expf(te[2])
                    + __uint_as_float((unsigned)q3) * __expf(te[3]);
        double lpart = 0.0;
        for (int t = tid; t < S_LEN; t += TPB)
            lpart += log((double)__ldcg(&g_Mbuf[t]));

        float* redf = reinterpret_cast<float*>(vbuf);
        redf[tid] = dpart;
        redd[tid] = lpart;
        __syncthreads();
        for (int off = TPB / 2; off > 0; off >>= 1) {
            if (tid < off) { redf[tid] += redf[tid + off]; redd[tid] += redd[tid + off]; }
            __syncthreads();
        }
        if (tid == 0)
            out[0] = (float)(redd[0] + log((double)redf[0]) -
                             (double)S_LEN * log((double)ALPHA));
    }
}

extern "C" void kernel_launch(void* const* d_in, const int* in_sizes, int n_in,
                              void* d_out, int out_size) {
    const float* a = (const float*)d_in[0];
    const float* bb = (const float*)d_in[1];
    const float* h;
    const float* tr;
    if (in_sizes[0] == S_LEN * TAGS) { h = a; tr = bb; }
    else { h = bb; tr = a; }

    crf_init<<<8, 256>>>();
    crf_main<<<NB, TPB>>>(h, tr, (float*)d_out);
}

// round 11
// speedup vs baseline: 3.2357x; 1.8242x over previous
#include <cuda_runtime.h>
#include <cuda_fp16.h>
#include <math.h>

#define S_LEN 8192
#define TAGS 2048
#define RPB 14
#define NB 147                 // 146*14 + 4 = 2048 rows
#define TPB 512
#define NWARP 16
#define JW (TAGS / NWARP)      // 128 j-columns per warp
#define JL (JW / 2)            // 64 j per lane
#define EH2 (JL / 2)           // 32 half2 E registers per lane
#define PSTRIDE 20
#define ALPHA 8.0f
#define START_IDX 0
#define END_IDX 1

typedef unsigned long long ull;

// Tagged carried vector: each word = {low: f32 bits of value, high: epoch}.
// Published with one atomic 8B relaxed store; the tag IS the readiness flag.
__device__ ull g_tag[2][TAGS];
__device__ float g_Mbuf[S_LEN];   // per-step global max (block 0 writes; epilogue reads)

__global__ void crf_init() {
    int i = blockIdx.x * blockDim.x + threadIdx.x;
    if (i < TAGS) {
        // buffer 0 holds r_0 (epoch 0): onehot(START_IDX)
        g_tag[0][i] = (i == START_IDX) ? (ull)0x3f800000u : 0ull;
        // buffer 1: epoch sentinel that never matches any t in [0, S_LEN]
        g_tag[1][i] = 0xFFFFFFFF00000000ull;
    }
}

__device__ __forceinline__ __half2 f_as_h2(const float& f) {
    return *reinterpret_cast<const __half2*>(&f);
}
__device__ __forceinline__ float4 add4(float4 a, float4 b) {
    return make_float4(a.x + b.x, a.y + b.y, a.z + b.z, a.w + b.w);
}
__device__ __forceinline__ unsigned umax2(unsigned a, unsigned b) { return a > b ? a : b; }

__global__ void __launch_bounds__(TPB, 1) crf_main(const float* __restrict__ h,
                                                   const float* __restrict__ tr,
                                                   float* __restrict__ out) {
    __shared__ __half2 vbuf[TAGS / 2];          // 4KB: scaled fp16 vector (warp-private slices)
    __shared__ float P[2 * RPB][PSTRIDE];       // transposed partials
    __shared__ unsigned wmax[NWARP];            // per-warp value-max
    __shared__ double redd[TPB];                // epilogue scratch

    const int tid = threadIdx.x;
    const int warp = tid >> 5, lane = tid & 31;
    const int b = blockIdx.x;
    const int row0 = b * RPB;
    int nrows = TAGS - row0; if (nrows > RPB) nrows = RPB;

    const bool act = lane < 2 * RPB;
    const int row = (lane < RPB) ? lane : lane - RPB;
    const int jh = (lane >= RPB) ? 1 : 0;

    // ---- One-time: this lane's E chunk = exp(transitions) -> 32 half2 registers ----
    __half2 E2[EH2];
    if (act && row < nrows) {
        const float* trow = tr + (size_t)(row0 + row) * TAGS + warp * JW + jh * JL;
#pragma unroll
        for (int q = 0; q < EH2; q++)
            E2[q] = __floats2half2_rn(__expf(trow[2 * q]), __expf(trow[2 * q + 1]));
    } else {
#pragma unroll
        for (int q = 0; q < EH2; q++) E2[q] = __floats2half2_rn(0.f, 0.f);
    }

    const float4* v4base = reinterpret_cast<const float4*>(vbuf) + (warp * 16 + jh * 8);
    const bool comb = (warp == 0) && (lane < nrows);

    float hv = comb ? __ldcg(h + row0 + lane) : 0.f;   // one step ahead

    for (int t = 0; t < S_LEN; t++) {
        // ---- off critical path: exp of current emissions, prefetch next step's ----
        float ehv = __expf(hv);
        if (comb && t + 1 < S_LEN)
            hv = __ldcg(h + (size_t)(t + 1) * TAGS + row0 + lane);

        const unsigned tu = (unsigned)t;

        // ---- gate: ONE lane per warp spins on one tag in the warp's range ----
        if (lane == 0) {
            const ull* probe = &g_tag[t & 1][warp << 7];   // first tag of warp's 128
            ull pq;
            for (;;) {
                asm volatile("ld.relaxed.gpu.global.b64 %0, [%1];"
                             : "=l"(pq) : "l"(probe) : "memory");
                if ((unsigned)(pq >> 32) == tu) break;
                __nanosleep(40);
            }
        }
        __syncwarp();

        // ---- verify + load own 4 tagged values (usually one iteration) ----
        const ull* src = &g_tag[t & 1][4 * tid];
        ull q0, q1, q2, q3;
        do {
            asm volatile("ld.relaxed.gpu.global.b64 %0, [%1];" : "=l"(q0) : "l"(src) : "memory");
            asm volatile("ld.relaxed.gpu.global.b64 %0, [%1];" : "=l"(q1) : "l"(src + 1) : "memory");
            asm volatile("ld.relaxed.gpu.global.b64 %0, [%1];" : "=l"(q2) : "l"(src + 2) : "memory");
            asm volatile("ld.relaxed.gpu.global.b64 %0, [%1];" : "=l"(q3) : "l"(src + 3) : "memory");
        } while ((unsigned)(q0 >> 32) != tu || (unsigned)(q1 >> 32) != tu ||
                 (unsigned)(q2 >> 32) != tu || (unsigned)(q3 >> 32) != tu);

        // ---- block-wide max of r_t (values >= 0: uint order == float order) ----
        unsigned u = umax2(umax2((unsigned)q0, (unsigned)q1),
                           umax2((unsigned)q2, (unsigned)q3));
        u = __reduce_max_sync(0xffffffffu, u);
        if (lane == 0) wmax[warp] = u;
        __syncthreads();
        uint4 A = *reinterpret_cast<const uint4*>(wmax);
        uint4 B = *reinterpret_cast<const uint4*>(wmax + 4);
        uint4 C = *reinterpret_cast<const uint4*>(wmax + 8);
        uint4 D = *reinterpret_cast<const uint4*>(wmax + 12);
        unsigned mm = umax2(umax2(umax2(A.x, A.y), umax2(A.z, A.w)),
                            umax2(umax2(umax2(B.x, B.y), umax2(B.z, B.w)),
                                  umax2(umax2(umax2(C.x, C.y), umax2(C.z, C.w)),
                                        umax2(umax2(D.x, D.y), umax2(D.z, D.w)))));
        float m = __uint_as_float(mm);
        if (b == 0 && tid == 0) __stcg(&g_Mbuf[t], m);

        // ---- scale + fp16 convert own 4 values into warp-private vbuf slice ----
        float s = __fdividef(ALPHA, m);
        vbuf[2 * tid] = __floats2half2_rn(__uint_as_float((unsigned)q0) * s,
                                          __uint_as_float((unsigned)q1) * s);
        vbuf[2 * tid + 1] = __floats2half2_rn(__uint_as_float((unsigned)q2) * s,
                                              __uint_as_float((unsigned)q3) * s);
        __syncwarp();

        // ---- 64-j dot fragment per lane: 4 chains of 8 half2 ----
        float f0 = 0.f, f1 = 0.f;
#pragma unroll
        for (int c = 0; c < 4; c++) {
            float4 va = v4base[2 * c];
            float4 vb = v4base[2 * c + 1];
            __half2 acc = __hmul2(E2[8 * c + 0], f_as_h2(va.x));
            acc = __hfma2(E2[8 * c + 1], f_as_h2(va.y), acc);
            acc = __hfma2(E2[8 * c + 2], f_as_h2(va.z), acc);
            acc = __hfma2(E2[8 * c + 3], f_as_h2(va.w), acc);
            acc = __hfma2(E2[8 * c + 4], f_as_h2(vb.x), acc);
            acc = __hfma2(E2[8 * c + 5], f_as_h2(vb.y), acc);
            acc = __hfma2(E2[8 * c + 6], f_as_h2(vb.z), acc);
            acc = __hfma2(E2[8 * c + 7], f_as_h2(vb.w), acc);
            float2 ff = __half22float2(acc);
            f0 += ff.x; f1 += ff.y;
        }
        if (act) P[lane][warp] = f0 + f1;
        __syncthreads();

        // ---- combine (warp 0) and publish tagged values of r_{t+1} ----
        if (comb) {
            const float4* Pr = reinterpret_cast<const float4*>(P[lane]);
            const float4* Qr = reinterpret_cast<const float4*>(P[lane + RPB]);
            float4 s4 = add4(add4(add4(Pr[0], Pr[1]), add4(Pr[2], Pr[3])),
                             add4(add4(Qr[0], Qr[1]), add4(Qr[2], Qr[3])));
            float sum = (s4.x + s4.y) + (s4.z + s4.w);
            float wv = ehv * sum;
            ull pub = ((ull)(unsigned)(t + 1) << 32) | (ull)__float_as_uint(wv);
            asm volatile("st.relaxed.gpu.global.b64 [%0], %1;"
                         :: "l"(&g_tag[(t + 1) & 1][row0 + lane]), "l"(pub) : "memory");
        }
        // (next iteration's polls + syncthreads gate smem reuse)
    }

    // ---- epilogue: block 0 gathers r_S and computes log Z ----
    if (b == 0) {
        const ull* src = &g_tag[S_LEN & 1][4 * tid];
        const unsigned tu = (unsigned)S_LEN;
        ull q0, q1, q2, q3;
        do {
            asm volatile("ld.relaxed.gpu.global.b64 %0, [%1];" : "=l"(q0) : "l"(src) : "memory");
            asm volatile("ld.relaxed.gpu.global.b64 %0, [%1];" : "=l"(q1) : "l"(src + 1) : "memory");
            asm volatile("ld.relaxed.gpu.global.b64 %0, [%1];" : "=l"(q2) : "l"(src + 2) : "memory");
            asm volatile("ld.relaxed.gpu.global.b64 %0, [%1];" : "=l"(q3) : "l"(src + 3) : "memory");
        } while ((unsigned)(q0 >> 32) != tu || (unsigned)(q1 >> 32) != tu ||
                 (unsigned)(q2 >> 32) != tu || (unsigned)(q3 >> 32) != tu);

        const float* te = tr + (size_t)END_IDX * TAGS + 4 * tid;
        float dpart = __uint_as_float((unsigned)q0) * __expf(te[0])
                    + __uint_as_float((unsigned)q1) * __expf(te[1])
                    + __uint_as_float((unsigned)q2) * __expf(te[2])
                    + __uint_as_float((unsigned)q3) * __expf(te[3]);
        double lpart = 0.0;
        for (int t = tid; t < S_LEN; t += TPB)
            lpart += log((double)__ldcg(&g_Mbuf[t]));

        float* redf = reinterpret_cast<float*>(vbuf);
        redf[tid] = dpart;
        redd[tid] = lpart;
        __syncthreads();
        for (int off = TPB / 2; off > 0; off >>= 1) {
            if (tid < off) { redf[tid] += redf[tid + off]; redd[tid] += redd[tid + off]; }
            __syncthreads();
        }
        if (tid == 0)
            out[0] = (float)(redd[0] + log((double)redf[0]) -
                             (double)S_LEN * log((double)ALPHA));
    }
}

extern "C" void kernel_launch(void* const* d_in, const int* in_sizes, int n_in,
                              void* d_out, int out_size) {
    const float* a = (const float*)d_in[0];
    const float* bb = (const float*)d_in[1];
    const float* h;
    const float* tr;
    if (in_sizes[0] == S_LEN * TAGS) { h = a; tr = bb; }
    else { h = bb; tr = a; }

    crf_init<<<8, 256>>>();
    crf_main<<<NB, TPB>>>(h, tr, (float*)d_out);
}